// round 3
// baseline (speedup 1.0000x reference)
#include <cuda_runtime.h>
#include <math.h>

// Problem constants
#define Bc      4
#define Lc      2048
#define Dc      1024
#define DIc     2048
#define TWO_DIc 4096
#define Nc      16
#define Kc      4
#define Rc      64
#define RNc     96    // R + 2N

// Scratch (allocation-free rule: __device__ globals)
__device__ float g_xz [(size_t)Bc * Lc * TWO_DIc];  // 134 MB
__device__ float g_xc [(size_t)Bc * Lc * DIc];      //  67 MB
__device__ float g_dbl[(size_t)Bc * Lc * RNc];      //   3 MB
__device__ float g_dt [(size_t)Bc * Lc * DIc];      //  67 MB
__device__ float g_y  [(size_t)Bc * Lc * DIc];      //  67 MB

// ---------------------------------------------------------------------------
// Generic NT SGEMM: C[m,n] = sum_k A[m*lda+k] * Bw[n*ldb+k]  (both K-contiguous)
// EPI==1: softplus(acc + bias[n])
// ---------------------------------------------------------------------------
template<int BM, int BN, int BK, int TM, int TN, int EPI>
__global__ __launch_bounds__((BM / TM) * (BN / TN))
void gemm_nt(const float* __restrict__ A, int lda,
             const float* __restrict__ Bw, int ldb,
             float* __restrict__ C, int ldc,
             int M, int Nn, int K,
             const float* __restrict__ bias)
{
    constexpr int THREADS     = (BM / TM) * (BN / TN);
    constexpr int VEC_PER_ROW = BK / 4;                 // float4s per K-row
    constexpr int ROW_STRIDE  = THREADS / VEC_PER_ROW;  // tile rows per load wave

    __shared__ float As[BK][BM];
    __shared__ float Bs[BK][BN];

    const int tid = threadIdx.x;
    const int tx  = tid % (BN / TN);
    const int ty  = tid / (BN / TN);
    const int bm  = blockIdx.y * BM;
    const int bn  = blockIdx.x * BN;

    const int lr = tid / VEC_PER_ROW;        // row within tile for loading
    const int lc = (tid % VEC_PER_ROW) * 4;  // k offset within tile

    float acc[TM][TN] = {};

    for (int kt = 0; kt < K; kt += BK) {
        // Load A tile, store transposed As[k][m]
        #pragma unroll
        for (int r = 0; r < BM; r += ROW_STRIDE) {
            const float4 v = *reinterpret_cast<const float4*>(
                &A[(size_t)(bm + r + lr) * lda + kt + lc]);
            As[lc + 0][r + lr] = v.x;
            As[lc + 1][r + lr] = v.y;
            As[lc + 2][r + lr] = v.z;
            As[lc + 3][r + lr] = v.w;
        }
        // Load B tile (guard N), store transposed Bs[k][n]
        #pragma unroll
        for (int r = 0; r < BN; r += ROW_STRIDE) {
            const int n = bn + r + lr;
            float4 v = make_float4(0.f, 0.f, 0.f, 0.f);
            if (n < Nn)
                v = *reinterpret_cast<const float4*>(
                    &Bw[(size_t)n * ldb + kt + lc]);
            Bs[lc + 0][r + lr] = v.x;
            Bs[lc + 1][r + lr] = v.y;
            Bs[lc + 2][r + lr] = v.z;
            Bs[lc + 3][r + lr] = v.w;
        }
        __syncthreads();

        const float* __restrict__ asp = &As[0][ty * TM];
        const float* __restrict__ bsp = &Bs[0][tx * TN];
        #pragma unroll
        for (int k = 0; k < BK; ++k) {
            float am[TM], bv[TN];
            #pragma unroll
            for (int i = 0; i < TM; ++i) am[i] = asp[k * BM + i];
            #pragma unroll
            for (int j = 0; j < TN; ++j) bv[j] = bsp[k * BN + j];
            #pragma unroll
            for (int i = 0; i < TM; ++i)
                #pragma unroll
                for (int j = 0; j < TN; ++j)
                    acc[i][j] = fmaf(am[i], bv[j], acc[i][j]);
        }
        __syncthreads();
    }

    #pragma unroll
    for (int i = 0; i < TM; ++i) {
        const int row = bm + ty * TM + i;
        #pragma unroll
        for (int j = 0; j < TN; ++j) {
            const int col = bn + tx * TN + j;
            if (col < Nn) {
                float v = acc[i][j];
                if (EPI == 1) {
                    v += bias[col];
                    v = (v > 20.f) ? v : log1pf(__expf(v));
                }
                C[(size_t)row * ldc + col] = v;
            }
        }
    }
}

// ---------------------------------------------------------------------------
// Depthwise causal conv (K=4) + bias + silu:  xc = silu(conv(xi) + conv_b)
// xi = first DI columns of xz
// ---------------------------------------------------------------------------
__global__ void conv_silu_kernel(const float* __restrict__ xz,
                                 const float* __restrict__ conv_w,
                                 const float* __restrict__ conv_b,
                                 float* __restrict__ xc)
{
    const int d = blockIdx.x * blockDim.x + threadIdx.x;
    const int l = blockIdx.y;
    const int b = blockIdx.z;

    float accv = conv_b[d];
    #pragma unroll
    for (int k = 0; k < Kc; ++k) {
        const int ls = l - (Kc - 1) + k;
        if (ls >= 0)
            accv = fmaf(xz[((size_t)b * Lc + ls) * TWO_DIc + d],
                        conv_w[d * Kc + k], accv);
    }
    const float s = accv / (1.f + __expf(-accv));
    xc[((size_t)b * Lc + l) * DIc + d] = s;
}

// ---------------------------------------------------------------------------
// Selective scan. 16 lanes per (b,d) channel — one lane per state n.
// h_n <- exp(dt*A_n)*h_n + dt*B_n*xc ;  y = sum_n h_n*C_n  (shfl-xor reduce)
// Epilogue fused: y = (y + xc*D) * silu(z)
// ---------------------------------------------------------------------------
__global__ void scan_kernel(const float* __restrict__ dt,
                            const float* __restrict__ dbl,
                            const float* __restrict__ xc,
                            const float* __restrict__ xz,
                            const float* __restrict__ A_log,
                            const float* __restrict__ D_param,
                            float* __restrict__ y)
{
    const int gid  = blockIdx.x * (blockDim.x >> 4) + (threadIdx.x >> 4);
    const int lane = threadIdx.x & 15;
    const int b = gid / DIc;
    const int d = gid % DIc;

    const float An = -__expf(A_log[d * Nc + lane]);
    const float Dd = D_param[d];
    float h = 0.f;

    const float* dt_p = dt  + (size_t)b * Lc * DIc + d;
    const float* xc_p = xc  + (size_t)b * Lc * DIc + d;
    const float* z_p  = xz  + (size_t)b * Lc * TWO_DIc + DIc + d;
    const float* bc_p = dbl + (size_t)b * Lc * RNc + Rc;
    float*       y_p  = y   + (size_t)b * Lc * DIc + d;

    for (int l = 0; l < Lc; ++l) {
        const float dtv = dt_p[(size_t)l * DIc];
        const float xcv = xc_p[(size_t)l * DIc];
        const float Bn  = bc_p[(size_t)l * RNc + lane];
        const float Cn  = bc_p[(size_t)l * RNc + Nc + lane];

        const float dA = __expf(dtv * An);
        h = fmaf(dA, h, dtv * Bn * xcv);

        float v = h * Cn;
        v += __shfl_xor_sync(0xffffffffu, v, 8);
        v += __shfl_xor_sync(0xffffffffu, v, 4);
        v += __shfl_xor_sync(0xffffffffu, v, 2);
        v += __shfl_xor_sync(0xffffffffu, v, 1);

        if (lane == 0) {
            const float zv = z_p[(size_t)l * TWO_DIc];
            float yv = v + xcv * Dd;
            yv = yv * (zv / (1.f + __expf(-zv)));
            y_p[(size_t)l * DIc] = yv;
        }
    }
}

// ---------------------------------------------------------------------------
extern "C" void kernel_launch(void* const* d_in, const int* in_sizes, int n_in,
                              void* d_out, int out_size)
{
    const float* x       = (const float*)d_in[0];
    const float* W_in    = (const float*)d_in[1];
    const float* conv_w  = (const float*)d_in[2];
    const float* conv_b  = (const float*)d_in[3];
    const float* W_xproj = (const float*)d_in[4];
    const float* W_dt    = (const float*)d_in[5];
    const float* dt_bias = (const float*)d_in[6];
    const float* A_log   = (const float*)d_in[7];
    const float* D_param = (const float*)d_in[8];
    const float* W_out   = (const float*)d_in[9];
    float* out = (float*)d_out;

    float *xz, *xc, *dbl, *dtb, *yb;
    cudaGetSymbolAddress((void**)&xz,  g_xz);
    cudaGetSymbolAddress((void**)&xc,  g_xc);
    cudaGetSymbolAddress((void**)&dbl, g_dbl);
    cudaGetSymbolAddress((void**)&dtb, g_dt);
    cudaGetSymbolAddress((void**)&yb,  g_y);

    const int M = Bc * Lc;  // 8192

    // GEMM1: xz[M, 4096] = x[M,1024] @ W_in[4096,1024]^T
    gemm_nt<128, 128, 16, 8, 8, 0><<<dim3(TWO_DIc / 128, M / 128), 256>>>(
        x, Dc, W_in, Dc, xz, TWO_DIc, M, TWO_DIc, Dc, nullptr);

    // Depthwise causal conv + silu -> xc
    conv_silu_kernel<<<dim3(DIc / 256, Lc, Bc), 256>>>(xz, conv_w, conv_b, xc);

    // GEMM2: dbl[M, 96] = xc[M,2048] @ W_xproj[96,2048]^T
    gemm_nt<64, 128, 16, 4, 8, 0><<<dim3(1, M / 64), 256>>>(
        xc, DIc, W_xproj, DIc, dbl, RNc, M, RNc, DIc, nullptr);

    // GEMM3: dt[M, 2048] = softplus(dt_raw[M,64] @ W_dt[2048,64]^T + dt_bias)
    //        (dt_raw = first 64 cols of dbl, lda = 96)
    gemm_nt<128, 128, 16, 8, 8, 1><<<dim3(DIc / 128, M / 128), 256>>>(
        dbl, RNc, W_dt, Rc, dtb, DIc, M, DIc, Rc, dt_bias);

    // Selective scan + fused gating epilogue -> yb
    scan_kernel<<<(Bc * DIc) / 16, 256>>>(dtb, dbl, xc, xz, A_log, D_param, yb);

    // GEMM4: out[M, 1024] = yb[M,2048] @ W_out[1024,2048]^T
    gemm_nt<128, 128, 16, 8, 8, 0><<<dim3(Dc / 128, M / 128), 256>>>(
        yb, DIc, W_out, DIc, out, Dc, M, Dc, DIc, nullptr);
}

// round 4
// speedup vs baseline: 1.3769x; 1.3769x over previous
#include <cuda_runtime.h>
#include <math.h>

// Problem constants
#define Bc      4
#define Lc      2048
#define Dc      1024
#define DIc     2048
#define TWO_DIc 4096
#define Nc      16
#define Kc      4
#define Rc      64
#define RNc     96    // R + 2N

// Scratch (allocation-free rule: __device__ globals)
__device__ float g_xz [(size_t)Bc * Lc * TWO_DIc];  // 134 MB
__device__ float g_xc [(size_t)Bc * Lc * DIc];      //  67 MB
__device__ float g_dbl[(size_t)Bc * Lc * RNc];      //   3 MB
__device__ float g_dt [(size_t)Bc * Lc * DIc];      //  67 MB
__device__ float g_y  [(size_t)Bc * Lc * DIc];      //  67 MB

// ---------------------------------------------------------------------------
// Packed f32x2 helpers (sm_100+): 2 fp32 FMAs per instruction, bit-exact fp32
// ---------------------------------------------------------------------------
__device__ __forceinline__ unsigned long long pk2(float lo, float hi) {
    unsigned long long r;
    asm("mov.b64 %0, {%1, %2};" : "=l"(r) : "f"(lo), "f"(hi));
    return r;
}
__device__ __forceinline__ void fma2(unsigned long long& d,
                                     unsigned long long a, unsigned long long b) {
    asm("fma.rn.f32x2 %0, %1, %2, %0;" : "+l"(d) : "l"(a), "l"(b));
}
__device__ __forceinline__ float2 upk2(unsigned long long v) {
    float2 f;
    asm("mov.b64 {%0, %1}, %2;" : "=f"(f.x), "=f"(f.y) : "l"(v));
    return f;
}

// ---------------------------------------------------------------------------
// NT SGEMM, double-buffered smem + reg-staged gmem prefetch, packed f32x2 math.
// C[m,n] = sum_k A[m*lda+k] * Bw[n*ldb+k].  EPI==1: softplus(acc + bias[n]).
// Requires: M % BM == 0, K % BK == 0 (true for all call sites); N guarded.
// ---------------------------------------------------------------------------
template<int BM, int BN, int BK, int TM, int TN, int EPI>
__global__ __launch_bounds__((BM / TM) * (BN / TN), 2)
void gemm_nt(const float* __restrict__ A, int lda,
             const float* __restrict__ Bw, int ldb,
             float* __restrict__ C, int ldc,
             int M, int Nn, int K,
             const float* __restrict__ bias)
{
    constexpr int THREADS = (BM / TM) * (BN / TN);
    constexpr int VPR     = BK / 4;        // float4s per K-row
    constexpr int RS      = THREADS / VPR; // tile rows per load wave
    constexpr int AR      = BM / RS;       // staged float4s (A) per thread
    constexpr int BR      = BN / RS;       // staged float4s (B) per thread
    constexpr int LDA_S   = BM + 4;        // +4 pad: halves STS bank conflicts
    constexpr int LDB_S   = BN + 4;

    __shared__ float As[2][BK][LDA_S];
    __shared__ float Bs[2][BK][LDB_S];

    const int tid = threadIdx.x;
    const int tx  = tid % (BN / TN);
    const int ty  = tid / (BN / TN);
    const int bm  = blockIdx.y * BM;
    const int bn  = blockIdx.x * BN;
    const int lr  = tid / VPR;
    const int lc  = (tid % VPR) * 4;

    unsigned long long acc[TM][TN / 2] = {};   // zero bits == +0.0f pairs
    float4 ar[AR], br[BR];

    auto ldg = [&](int kt) {
        #pragma unroll
        for (int i = 0; i < AR; ++i)
            ar[i] = *reinterpret_cast<const float4*>(
                &A[(size_t)(bm + i * RS + lr) * lda + kt + lc]);
        #pragma unroll
        for (int i = 0; i < BR; ++i) {
            const int n = bn + i * RS + lr;
            br[i] = (n < Nn)
                  ? *reinterpret_cast<const float4*>(
                        &Bw[(size_t)n * ldb + kt + lc])
                  : make_float4(0.f, 0.f, 0.f, 0.f);
        }
    };
    auto sts = [&](int s) {
        #pragma unroll
        for (int i = 0; i < AR; ++i) {
            As[s][lc + 0][i * RS + lr] = ar[i].x;
            As[s][lc + 1][i * RS + lr] = ar[i].y;
            As[s][lc + 2][i * RS + lr] = ar[i].z;
            As[s][lc + 3][i * RS + lr] = ar[i].w;
        }
        #pragma unroll
        for (int i = 0; i < BR; ++i) {
            Bs[s][lc + 0][i * RS + lr] = br[i].x;
            Bs[s][lc + 1][i * RS + lr] = br[i].y;
            Bs[s][lc + 2][i * RS + lr] = br[i].z;
            Bs[s][lc + 3][i * RS + lr] = br[i].w;
        }
    };

    // Prologue: stage tile 0
    ldg(0);
    sts(0);
    __syncthreads();

    const int nt = K / BK;
    for (int t = 0; t < nt; ++t) {
        const int cur = t & 1;
        if (t + 1 < nt) ldg((t + 1) * BK);   // prefetch overlaps compute below

        #pragma unroll
        for (int k = 0; k < BK; ++k) {
            float4 af[TM / 4], bf[TN / 4];
            #pragma unroll
            for (int i = 0; i < TM / 4; ++i)
                af[i] = *reinterpret_cast<const float4*>(
                    &As[cur][k][ty * TM + 4 * i]);
            #pragma unroll
            for (int j = 0; j < TN / 4; ++j)
                bf[j] = *reinterpret_cast<const float4*>(
                    &Bs[cur][k][tx * TN + 4 * j]);

            unsigned long long bp[TN / 2];
            #pragma unroll
            for (int j = 0; j < TN / 4; ++j) {
                bp[2 * j]     = pk2(bf[j].x, bf[j].y);
                bp[2 * j + 1] = pk2(bf[j].z, bf[j].w);
            }
            const float* afs = reinterpret_cast<const float*>(af);
            #pragma unroll
            for (int i = 0; i < TM; ++i) {
                const unsigned long long a2 = pk2(afs[i], afs[i]);
                #pragma unroll
                for (int j = 0; j < TN / 2; ++j)
                    fma2(acc[i][j], a2, bp[j]);
            }
        }

        if (t + 1 < nt) sts((t + 1) & 1);    // other buffer: no reader this iter
        __syncthreads();
    }

    // Epilogue
    #pragma unroll
    for (int i = 0; i < TM; ++i) {
        const int row = bm + ty * TM + i;
        #pragma unroll
        for (int j = 0; j < TN / 2; ++j) {
            const int col = bn + tx * TN + 2 * j;
            if (col < Nn) {   // Nn even, col even -> pair fully in-bounds
                float2 p = upk2(acc[i][j]);
                if (EPI == 1) {
                    p.x += bias[col];
                    p.x = (p.x > 20.f) ? p.x : log1pf(__expf(p.x));
                    p.y += bias[col + 1];
                    p.y = (p.y > 20.f) ? p.y : log1pf(__expf(p.y));
                }
                *reinterpret_cast<float2*>(&C[(size_t)row * ldc + col]) = p;
            }
        }
    }
}

// ---------------------------------------------------------------------------
// Depthwise causal conv (K=4) + bias + silu:  xc = silu(conv(xi) + conv_b)
// ---------------------------------------------------------------------------
__global__ void conv_silu_kernel(const float* __restrict__ xz,
                                 const float* __restrict__ conv_w,
                                 const float* __restrict__ conv_b,
                                 float* __restrict__ xc)
{
    const int d = blockIdx.x * blockDim.x + threadIdx.x;
    const int l = blockIdx.y;
    const int b = blockIdx.z;

    float accv = conv_b[d];
    #pragma unroll
    for (int k = 0; k < Kc; ++k) {
        const int ls = l - (Kc - 1) + k;
        if (ls >= 0)
            accv = fmaf(xz[((size_t)b * Lc + ls) * TWO_DIc + d],
                        conv_w[d * Kc + k], accv);
    }
    const float s = accv / (1.f + __expf(-accv));
    xc[((size_t)b * Lc + l) * DIc + d] = s;
}

// ---------------------------------------------------------------------------
// Selective scan. 16 lanes per (b,d) channel — one lane per state n.
// Manual software pipeline: next-iteration loads issue before current update.
// ---------------------------------------------------------------------------
__global__ void scan_kernel(const float* __restrict__ dt,
                            const float* __restrict__ dbl,
                            const float* __restrict__ xc,
                            const float* __restrict__ xz,
                            const float* __restrict__ A_log,
                            const float* __restrict__ D_param,
                            float* __restrict__ y)
{
    const int gid  = blockIdx.x * (blockDim.x >> 4) + (threadIdx.x >> 4);
    const int lane = threadIdx.x & 15;
    const int b = gid / DIc;
    const int d = gid % DIc;

    const float An = -__expf(A_log[d * Nc + lane]);
    const float Dd = D_param[d];
    float h = 0.f;

    const float* dt_p = dt  + (size_t)b * Lc * DIc + d;
    const float* xc_p = xc  + (size_t)b * Lc * DIc + d;
    const float* z_p  = xz  + (size_t)b * Lc * TWO_DIc + DIc + d;
    const float* bc_p = dbl + (size_t)b * Lc * RNc + Rc;
    float*       y_p  = y   + (size_t)b * Lc * DIc + d;

    float dtv = dt_p[0];
    float xcv = xc_p[0];
    float Bn  = bc_p[lane];
    float Cn  = bc_p[Nc + lane];
    float zv  = z_p[0];

    for (int l = 0; l < Lc; ++l) {
        float n_dt = 0.f, n_xc = 0.f, n_B = 0.f, n_C = 0.f, n_z = 0.f;
        if (l + 1 < Lc) {
            n_dt = dt_p[(size_t)(l + 1) * DIc];
            n_xc = xc_p[(size_t)(l + 1) * DIc];
            n_B  = bc_p[(size_t)(l + 1) * RNc + lane];
            n_C  = bc_p[(size_t)(l + 1) * RNc + Nc + lane];
            n_z  = z_p[(size_t)(l + 1) * TWO_DIc];
        }

        const float dA = __expf(dtv * An);
        h = fmaf(dA, h, dtv * Bn * xcv);

        float v = h * Cn;
        v += __shfl_xor_sync(0xffffffffu, v, 8);
        v += __shfl_xor_sync(0xffffffffu, v, 4);
        v += __shfl_xor_sync(0xffffffffu, v, 2);
        v += __shfl_xor_sync(0xffffffffu, v, 1);

        if (lane == 0) {
            float yv = v + xcv * Dd;
            yv = yv * (zv / (1.f + __expf(-zv)));
            y_p[(size_t)l * DIc] = yv;
        }

        dtv = n_dt; xcv = n_xc; Bn = n_B; Cn = n_C; zv = n_z;
    }
}

// ---------------------------------------------------------------------------
extern "C" void kernel_launch(void* const* d_in, const int* in_sizes, int n_in,
                              void* d_out, int out_size)
{
    const float* x       = (const float*)d_in[0];
    const float* W_in    = (const float*)d_in[1];
    const float* conv_w  = (const float*)d_in[2];
    const float* conv_b  = (const float*)d_in[3];
    const float* W_xproj = (const float*)d_in[4];
    const float* W_dt    = (const float*)d_in[5];
    const float* dt_bias = (const float*)d_in[6];
    const float* A_log   = (const float*)d_in[7];
    const float* D_param = (const float*)d_in[8];
    const float* W_out   = (const float*)d_in[9];
    float* out = (float*)d_out;

    float *xz, *xc, *dbl, *dtb, *yb;
    cudaGetSymbolAddress((void**)&xz,  g_xz);
    cudaGetSymbolAddress((void**)&xc,  g_xc);
    cudaGetSymbolAddress((void**)&dbl, g_dbl);
    cudaGetSymbolAddress((void**)&dtb, g_dt);
    cudaGetSymbolAddress((void**)&yb,  g_y);

    const int M = Bc * Lc;  // 8192

    // GEMM1: xz[M, 4096] = x[M,1024] @ W_in[4096,1024]^T
    gemm_nt<128, 128, 16, 8, 8, 0><<<dim3(TWO_DIc / 128, M / 128), 256>>>(
        x, Dc, W_in, Dc, xz, TWO_DIc, M, TWO_DIc, Dc, nullptr);

    // Depthwise causal conv + silu -> xc
    conv_silu_kernel<<<dim3(DIc / 256, Lc, Bc), 256>>>(xz, conv_w, conv_b, xc);

    // GEMM2: dbl[M, 96] = xc[M,2048] @ W_xproj[96,2048]^T
    gemm_nt<64, 128, 16, 4, 8, 0><<<dim3(1, M / 64), 256>>>(
        xc, DIc, W_xproj, DIc, dbl, RNc, M, RNc, DIc, nullptr);

    // GEMM3: dt[M, 2048] = softplus(dt_raw[M,64] @ W_dt[2048,64]^T + dt_bias)
    gemm_nt<128, 128, 16, 8, 8, 1><<<dim3(DIc / 128, M / 128), 256>>>(
        dbl, RNc, W_dt, Rc, dtb, DIc, M, DIc, Rc, dt_bias);

    // Selective scan + fused gating epilogue -> yb
    scan_kernel<<<(Bc * DIc) / 16, 256>>>(dtb, dbl, xc, xz, A_log, D_param, yb);

    // GEMM4: out[M, 1024] = yb[M,2048] @ W_out[1024,2048]^T
    gemm_nt<128, 128, 16, 8, 8, 0><<<dim3(Dc / 128, M / 128), 256>>>(
        yb, DIc, W_out, DIc, out, Dc, M, Dc, DIc, nullptr);
}

// round 6
// speedup vs baseline: 2.0766x; 1.5082x over previous
#include <cuda_runtime.h>
#include <cuda_bf16.h>
#include <math.h>
#include <stdint.h>

// Problem constants
#define Bc      4
#define Lc      2048
#define Dc      1024
#define DIc     2048
#define TWO_DIc 4096
#define Nc      16
#define Kc      4
#define Rc      64
#define RNc     96    // R + 2N

// fp32 scratch
__device__ float g_xz [(size_t)Bc * Lc * TWO_DIc];  // 134 MB
__device__ float g_xc [(size_t)Bc * Lc * DIc];      //  67 MB
__device__ float g_dbl[(size_t)Bc * Lc * RNc];      //   3 MB
__device__ float g_dt [(size_t)Bc * Lc * DIc];      //  67 MB

// bf16 split scratch (hi/lo) for tensor-core GEMMs
__device__ __nv_bfloat16 g_xhi [(size_t)Bc * Lc * Dc];
__device__ __nv_bfloat16 g_xlo [(size_t)Bc * Lc * Dc];
__device__ __nv_bfloat16 g_wihi[(size_t)TWO_DIc * Dc];
__device__ __nv_bfloat16 g_wilo[(size_t)TWO_DIc * Dc];
__device__ __nv_bfloat16 g_yhi [(size_t)Bc * Lc * DIc];
__device__ __nv_bfloat16 g_ylo [(size_t)Bc * Lc * DIc];
__device__ __nv_bfloat16 g_wohi[(size_t)Dc * DIc];
__device__ __nv_bfloat16 g_wolo[(size_t)Dc * DIc];

// ---------------------------------------------------------------------------
// Helpers
// ---------------------------------------------------------------------------
__device__ __forceinline__ uint32_t smem_u32(const void* p) {
    uint32_t a;
    asm("{ .reg .u64 t; cvta.to.shared.u64 t, %1; cvt.u32.u64 %0, t; }"
        : "=r"(a) : "l"(p));
    return a;
}
__device__ __forceinline__ void cpa16(uint32_t dst, const void* src) {
    asm volatile("cp.async.cg.shared.global [%0], [%1], 16;"
                 :: "r"(dst), "l"(src) : "memory");
}
__device__ __forceinline__ void mma_bf16(float* c, const uint32_t* a, const uint32_t* b) {
    asm volatile(
        "mma.sync.aligned.m16n8k16.row.col.f32.bf16.bf16.f32 "
        "{%0,%1,%2,%3}, {%4,%5,%6,%7}, {%8,%9}, {%0,%1,%2,%3};"
        : "+f"(c[0]), "+f"(c[1]), "+f"(c[2]), "+f"(c[3])
        : "r"(a[0]), "r"(a[1]), "r"(a[2]), "r"(a[3]), "r"(b[0]), "r"(b[1]));
}

// ---------------------------------------------------------------------------
// Split fp32 -> bf16 hi/lo   (n % 4 == 0)
// ---------------------------------------------------------------------------
__global__ void split_kernel(const float* __restrict__ src,
                             __nv_bfloat16* __restrict__ hi,
                             __nv_bfloat16* __restrict__ lo, int n)
{
    const int i = (blockIdx.x * blockDim.x + threadIdx.x) * 4;
    if (i >= n) return;
    const float4 v = *reinterpret_cast<const float4*>(src + i);
    __nv_bfloat16 h[4], l[4];
    const float f[4] = {v.x, v.y, v.z, v.w};
    #pragma unroll
    for (int j = 0; j < 4; ++j) {
        h[j] = __float2bfloat16(f[j]);
        l[j] = __float2bfloat16(f[j] - __bfloat162float(h[j]));
    }
    *reinterpret_cast<__nv_bfloat162*>(hi + i)     = __nv_bfloat162(h[0], h[1]);
    *reinterpret_cast<__nv_bfloat162*>(hi + i + 2) = __nv_bfloat162(h[2], h[3]);
    *reinterpret_cast<__nv_bfloat162*>(lo + i)     = __nv_bfloat162(l[0], l[1]);
    *reinterpret_cast<__nv_bfloat162*>(lo + i + 2) = __nv_bfloat162(l[2], l[3]);
}

// ---------------------------------------------------------------------------
// Split-bf16 tensor-core GEMM via mma.sync (legacy HMMA path, compute_100-safe)
//   C[m,n] = A[m,:]·B[n,:]  (NT, both K-contiguous)
//   3 passes: Ahi*Bhi + Ahi*Blo + Alo*Bhi, fp32 accumulate.
// CTA 128x128, BK=32 bf16; 8 warps (2x4), warp tile 64x32; cp.async double buffer.
// Requires M%128==0, N%128==0, K%32==0.
// Smem per stage: 4 matrices x 128 rows x 40 bf16 (80B row stride) = 40960 B.
// ---------------------------------------------------------------------------
#define TSTAGE 40960
#define TROW   80      // smem row stride in bytes (40 bf16): conflict-free quads

__global__ __launch_bounds__(256)
void gemm_mma(const __nv_bfloat16* __restrict__ Ahi,
              const __nv_bfloat16* __restrict__ Alo,
              const __nv_bfloat16* __restrict__ Bhi,
              const __nv_bfloat16* __restrict__ Blo,
              float* __restrict__ C, int K, int ldc)
{
    extern __shared__ char smem[];
    const uint32_t sm0 = smem_u32(smem);
    const int tid  = threadIdx.x;
    const int wid  = tid >> 5;
    const int lane = tid & 31;
    const int wm   = wid >> 2;          // 0..1 -> m offset wm*64
    const int wn   = wid & 3;           // 0..3 -> n offset wn*32
    const int bm   = blockIdx.y * 128;
    const int bn   = blockIdx.x * 128;
    const int g    = lane >> 2;         // 0..7
    const int q    = lane & 3;          // 0..3

    float acc[4][4][4] = {};            // [mt][nt][c0..c3]

    // Stage loader: 512 16B-chunks per matrix, 2 per thread per matrix
    auto stage_load = [&](int kt, int s) {
        const uint32_t sb = sm0 + s * TSTAGE;
        #pragma unroll
        for (int i = 0; i < 2; ++i) {
            const int idx = tid + 256 * i;
            const int row = idx >> 2;
            const int c4  = idx & 3;
            const uint32_t so = (uint32_t)row * TROW + c4 * 16;
            const size_t goA = (size_t)(bm + row) * K + kt + c4 * 8;
            const size_t goB = (size_t)(bn + row) * K + kt + c4 * 8;
            cpa16(sb + so,                 Ahi + goA);
            cpa16(sb + 10240 + so,         Alo + goA);
            cpa16(sb + 20480 + so,         Bhi + goB);
            cpa16(sb + 30720 + so,         Blo + goB);
        }
        asm volatile("cp.async.commit_group;" ::: "memory");
    };

    stage_load(0, 0);

    const int nt_iters = K / 32;
    for (int t = 0; t < nt_iters; ++t) {
        asm volatile("cp.async.wait_group 0;" ::: "memory");
        __syncthreads();
        if (t + 1 < nt_iters) stage_load((t + 1) * 32, (t + 1) & 1);

        const char* st = smem + (t & 1) * TSTAGE;
        #pragma unroll
        for (int ks = 0; ks < 2; ++ks) {
            const int kby = (ks * 16 + q * 2) * 2;   // byte offset of k within row

            uint32_t a_hi[4][4], a_lo[4][4];
            #pragma unroll
            for (int mt = 0; mt < 4; ++mt) {
                const char* ba = st + (size_t)(wm * 64 + mt * 16 + g) * TROW + kby;
                a_hi[mt][0] = *(const uint32_t*)(ba);
                a_hi[mt][1] = *(const uint32_t*)(ba + 8 * TROW);
                a_hi[mt][2] = *(const uint32_t*)(ba + 16);
                a_hi[mt][3] = *(const uint32_t*)(ba + 8 * TROW + 16);
                const char* bl = ba + 10240;
                a_lo[mt][0] = *(const uint32_t*)(bl);
                a_lo[mt][1] = *(const uint32_t*)(bl + 8 * TROW);
                a_lo[mt][2] = *(const uint32_t*)(bl + 16);
                a_lo[mt][3] = *(const uint32_t*)(bl + 8 * TROW + 16);
            }

            #pragma unroll
            for (int nt = 0; nt < 4; ++nt) {
                const char* bb = st + 20480 + (size_t)(wn * 32 + nt * 8 + g) * TROW + kby;
                uint32_t bh[2], bl2[2];
                bh[0]  = *(const uint32_t*)(bb);
                bh[1]  = *(const uint32_t*)(bb + 16);
                bl2[0] = *(const uint32_t*)(bb + 10240);
                bl2[1] = *(const uint32_t*)(bb + 10240 + 16);
                #pragma unroll
                for (int mt = 0; mt < 4; ++mt) {
                    mma_bf16(acc[mt][nt], a_hi[mt], bh);
                    mma_bf16(acc[mt][nt], a_hi[mt], bl2);
                    mma_bf16(acc[mt][nt], a_lo[mt], bh);
                }
            }
        }
        __syncthreads();
    }

    // Epilogue: fp32 stores, float2 per (reg-pair)
    #pragma unroll
    for (int mt = 0; mt < 4; ++mt) {
        const int r0 = bm + wm * 64 + mt * 16 + g;
        #pragma unroll
        for (int nt = 0; nt < 4; ++nt) {
            const int c0 = bn + wn * 32 + nt * 8 + q * 2;
            *reinterpret_cast<float2*>(&C[(size_t)r0 * ldc + c0]) =
                make_float2(acc[mt][nt][0], acc[mt][nt][1]);
            *reinterpret_cast<float2*>(&C[(size_t)(r0 + 8) * ldc + c0]) =
                make_float2(acc[mt][nt][2], acc[mt][nt][3]);
        }
    }
}

// ---------------------------------------------------------------------------
// Packed f32x2 helpers (sm_100+)
// ---------------------------------------------------------------------------
__device__ __forceinline__ unsigned long long pk2(float lo, float hi) {
    unsigned long long r;
    asm("mov.b64 %0, {%1, %2};" : "=l"(r) : "f"(lo), "f"(hi));
    return r;
}
__device__ __forceinline__ void fma2(unsigned long long& d,
                                     unsigned long long a, unsigned long long b) {
    asm("fma.rn.f32x2 %0, %1, %2, %0;" : "+l"(d) : "l"(a), "l"(b));
}
__device__ __forceinline__ float2 upk2(unsigned long long v) {
    float2 f;
    asm("mov.b64 {%0, %1}, %2;" : "=f"(f.x), "=f"(f.y) : "l"(v));
    return f;
}

// ---------------------------------------------------------------------------
// Scalar NT SGEMM (f32x2, double-buffered) — for GEMM2/GEMM3
// EPI==1: softplus(acc + bias[n])
// ---------------------------------------------------------------------------
template<int BM, int BN, int BK, int TM, int TN, int EPI>
__global__ __launch_bounds__((BM / TM) * (BN / TN), 2)
void gemm_nt(const float* __restrict__ A, int lda,
             const float* __restrict__ Bw, int ldb,
             float* __restrict__ C, int ldc,
             int M, int Nn, int K,
             const float* __restrict__ bias)
{
    constexpr int THREADS = (BM / TM) * (BN / TN);
    constexpr int VPR     = BK / 4;
    constexpr int RS      = THREADS / VPR;
    constexpr int AR      = BM / RS;
    constexpr int BR      = BN / RS;
    constexpr int LDA_S   = BM + 4;
    constexpr int LDB_S   = BN + 4;

    __shared__ float As[2][BK][LDA_S];
    __shared__ float Bs[2][BK][LDB_S];

    const int tid = threadIdx.x;
    const int tx  = tid % (BN / TN);
    const int ty  = tid / (BN / TN);
    const int bm  = blockIdx.y * BM;
    const int bn  = blockIdx.x * BN;
    const int lr  = tid / VPR;
    const int lc  = (tid % VPR) * 4;

    unsigned long long acc[TM][TN / 2] = {};
    float4 ar[AR], br[BR];

    auto ldg = [&](int kt) {
        #pragma unroll
        for (int i = 0; i < AR; ++i)
            ar[i] = *reinterpret_cast<const float4*>(
                &A[(size_t)(bm + i * RS + lr) * lda + kt + lc]);
        #pragma unroll
        for (int i = 0; i < BR; ++i) {
            const int n = bn + i * RS + lr;
            br[i] = (n < Nn)
                  ? *reinterpret_cast<const float4*>(&Bw[(size_t)n * ldb + kt + lc])
                  : make_float4(0.f, 0.f, 0.f, 0.f);
        }
    };
    auto sts = [&](int s) {
        #pragma unroll
        for (int i = 0; i < AR; ++i) {
            As[s][lc + 0][i * RS + lr] = ar[i].x;
            As[s][lc + 1][i * RS + lr] = ar[i].y;
            As[s][lc + 2][i * RS + lr] = ar[i].z;
            As[s][lc + 3][i * RS + lr] = ar[i].w;
        }
        #pragma unroll
        for (int i = 0; i < BR; ++i) {
            Bs[s][lc + 0][i * RS + lr] = br[i].x;
            Bs[s][lc + 1][i * RS + lr] = br[i].y;
            Bs[s][lc + 2][i * RS + lr] = br[i].z;
            Bs[s][lc + 3][i * RS + lr] = br[i].w;
        }
    };

    ldg(0);
    sts(0);
    __syncthreads();

    const int nt = K / BK;
    for (int t = 0; t < nt; ++t) {
        const int cur = t & 1;
        if (t + 1 < nt) ldg((t + 1) * BK);

        #pragma unroll
        for (int k = 0; k < BK; ++k) {
            float4 af[TM / 4], bf[TN / 4];
            #pragma unroll
            for (int i = 0; i < TM / 4; ++i)
                af[i] = *reinterpret_cast<const float4*>(&As[cur][k][ty * TM + 4 * i]);
            #pragma unroll
            for (int j = 0; j < TN / 4; ++j)
                bf[j] = *reinterpret_cast<const float4*>(&Bs[cur][k][tx * TN + 4 * j]);

            unsigned long long bp[TN / 2];
            #pragma unroll
            for (int j = 0; j < TN / 4; ++j) {
                bp[2 * j]     = pk2(bf[j].x, bf[j].y);
                bp[2 * j + 1] = pk2(bf[j].z, bf[j].w);
            }
            const float* afs = reinterpret_cast<const float*>(af);
            #pragma unroll
            for (int i = 0; i < TM; ++i) {
                const unsigned long long a2 = pk2(afs[i], afs[i]);
                #pragma unroll
                for (int j = 0; j < TN / 2; ++j)
                    fma2(acc[i][j], a2, bp[j]);
            }
        }

        if (t + 1 < nt) sts((t + 1) & 1);
        __syncthreads();
    }

    #pragma unroll
    for (int i = 0; i < TM; ++i) {
        const int row = bm + ty * TM + i;
        #pragma unroll
        for (int j = 0; j < TN / 2; ++j) {
            const int col = bn + tx * TN + 2 * j;
            if (col < Nn) {
                float2 p = upk2(acc[i][j]);
                if (EPI == 1) {
                    p.x += bias[col];
                    p.x = (p.x > 20.f) ? p.x : log1pf(__expf(p.x));
                    p.y += bias[col + 1];
                    p.y = (p.y > 20.f) ? p.y : log1pf(__expf(p.y));
                }
                *reinterpret_cast<float2*>(&C[(size_t)row * ldc + col]) = p;
            }
        }
    }
}

// ---------------------------------------------------------------------------
// Depthwise causal conv (K=4) + bias + silu
// ---------------------------------------------------------------------------
__global__ void conv_silu_kernel(const float* __restrict__ xz,
                                 const float* __restrict__ conv_w,
                                 const float* __restrict__ conv_b,
                                 float* __restrict__ xc)
{
    const int d = blockIdx.x * blockDim.x + threadIdx.x;
    const int l = blockIdx.y;
    const int b = blockIdx.z;

    float accv = conv_b[d];
    #pragma unroll
    for (int k = 0; k < Kc; ++k) {
        const int ls = l - (Kc - 1) + k;
        if (ls >= 0)
            accv = fmaf(xz[((size_t)b * Lc + ls) * TWO_DIc + d],
                        conv_w[d * Kc + k], accv);
    }
    const float s = accv / (1.f + __expf(-accv));
    xc[((size_t)b * Lc + l) * DIc + d] = s;
}

// ---------------------------------------------------------------------------
// Selective scan; emits y as bf16 hi/lo (A-operand of GEMM4)
// ---------------------------------------------------------------------------
__global__ void scan_kernel(const float* __restrict__ dt,
                            const float* __restrict__ dbl,
                            const float* __restrict__ xc,
                            const float* __restrict__ xz,
                            const float* __restrict__ A_log,
                            const float* __restrict__ D_param,
                            __nv_bfloat16* __restrict__ yhi,
                            __nv_bfloat16* __restrict__ ylo)
{
    const int gid  = blockIdx.x * (blockDim.x >> 4) + (threadIdx.x >> 4);
    const int lane = threadIdx.x & 15;
    const int b = gid / DIc;
    const int d = gid % DIc;

    const float An = -__expf(A_log[d * Nc + lane]);
    const float Dd = D_param[d];
    float h = 0.f;

    const float* dt_p = dt  + (size_t)b * Lc * DIc + d;
    const float* xc_p = xc  + (size_t)b * Lc * DIc + d;
    const float* z_p  = xz  + (size_t)b * Lc * TWO_DIc + DIc + d;
    const float* bc_p = dbl + (size_t)b * Lc * RNc + Rc;
    __nv_bfloat16* yh_p = yhi + (size_t)b * Lc * DIc + d;
    __nv_bfloat16* yl_p = ylo + (size_t)b * Lc * DIc + d;

    float dtv = dt_p[0];
    float xcv = xc_p[0];
    float Bn  = bc_p[lane];
    float Cn  = bc_p[Nc + lane];
    float zv  = z_p[0];

    for (int t = 0; t < Lc; ++t) {
        float n_dt = 0.f, n_xc = 0.f, n_B = 0.f, n_C = 0.f, n_z = 0.f;
        if (t + 1 < Lc) {
            n_dt = dt_p[(size_t)(t + 1) * DIc];
            n_xc = xc_p[(size_t)(t + 1) * DIc];
            n_B  = bc_p[(size_t)(t + 1) * RNc + lane];
            n_C  = bc_p[(size_t)(t + 1) * RNc + Nc + lane];
            n_z  = z_p[(size_t)(t + 1) * TWO_DIc];
        }

        const float dA = __expf(dtv * An);
        h = fmaf(dA, h, dtv * Bn * xcv);

        float v = h * Cn;
        v += __shfl_xor_sync(0xffffffffu, v, 8);
        v += __shfl_xor_sync(0xffffffffu, v, 4);
        v += __shfl_xor_sync(0xffffffffu, v, 2);
        v += __shfl_xor_sync(0xffffffffu, v, 1);

        if (lane == 0) {
            float yv = v + xcv * Dd;
            yv = yv * (zv / (1.f + __expf(-zv)));
            const __nv_bfloat16 hh = __float2bfloat16(yv);
            const __nv_bfloat16 ll = __float2bfloat16(yv - __bfloat162float(hh));
            yh_p[(size_t)t * DIc] = hh;
            yl_p[(size_t)t * DIc] = ll;
        }

        dtv = n_dt; xcv = n_xc; Bn = n_B; Cn = n_C; zv = n_z;
    }
}

// ---------------------------------------------------------------------------
extern "C" void kernel_launch(void* const* d_in, const int* in_sizes, int n_in,
                              void* d_out, int out_size)
{
    const float* x       = (const float*)d_in[0];
    const float* W_in    = (const float*)d_in[1];
    const float* conv_w  = (const float*)d_in[2];
    const float* conv_b  = (const float*)d_in[3];
    const float* W_xproj = (const float*)d_in[4];
    const float* W_dt    = (const float*)d_in[5];
    const float* dt_bias = (const float*)d_in[6];
    const float* A_log   = (const float*)d_in[7];
    const float* D_param = (const float*)d_in[8];
    const float* W_out   = (const float*)d_in[9];
    float* out = (float*)d_out;

    float *xz, *xc, *dbl, *dtb;
    __nv_bfloat16 *xhi, *xlo, *wihi, *wilo, *yhi, *ylo, *wohi, *wolo;
    cudaGetSymbolAddress((void**)&xz,   g_xz);
    cudaGetSymbolAddress((void**)&xc,   g_xc);
    cudaGetSymbolAddress((void**)&dbl,  g_dbl);
    cudaGetSymbolAddress((void**)&dtb,  g_dt);
    cudaGetSymbolAddress((void**)&xhi,  g_xhi);
    cudaGetSymbolAddress((void**)&xlo,  g_xlo);
    cudaGetSymbolAddress((void**)&wihi, g_wihi);
    cudaGetSymbolAddress((void**)&wilo, g_wilo);
    cudaGetSymbolAddress((void**)&yhi,  g_yhi);
    cudaGetSymbolAddress((void**)&ylo,  g_ylo);
    cudaGetSymbolAddress((void**)&wohi, g_wohi);
    cudaGetSymbolAddress((void**)&wolo, g_wolo);

    const int M = Bc * Lc;  // 8192
    const int TENSOR_SMEM = 2 * TSTAGE;  // 81920 B dynamic

    cudaFuncSetAttribute(gemm_mma,
                         cudaFuncAttributeMaxDynamicSharedMemorySize, TENSOR_SMEM);

    // Split inputs to bf16 hi/lo
    split_kernel<<<(M * Dc / 4 + 255) / 256, 256>>>(x, xhi, xlo, M * Dc);
    split_kernel<<<(TWO_DIc * Dc / 4 + 255) / 256, 256>>>(W_in, wihi, wilo, TWO_DIc * Dc);
    split_kernel<<<(Dc * DIc / 4 + 255) / 256, 256>>>(W_out, wohi, wolo, Dc * DIc);

    // GEMM1 (tensor): xz[M,4096] = x @ W_in^T
    gemm_mma<<<dim3(TWO_DIc / 128, M / 128), 256, TENSOR_SMEM>>>(
        xhi, xlo, wihi, wilo, xz, Dc, TWO_DIc);

    // Depthwise causal conv + silu -> xc
    conv_silu_kernel<<<dim3(DIc / 256, Lc, Bc), 256>>>(xz, conv_w, conv_b, xc);

    // GEMM2 (scalar): dbl[M,96] = xc @ W_xproj^T
    gemm_nt<64, 128, 16, 4, 8, 0><<<dim3(1, M / 64), 256>>>(
        xc, DIc, W_xproj, DIc, dbl, RNc, M, RNc, DIc, nullptr);

    // GEMM3 (scalar): dt[M,2048] = softplus(dbl[:, :64] @ W_dt^T + dt_bias)
    gemm_nt<128, 128, 16, 8, 8, 1><<<dim3(DIc / 128, M / 128), 256>>>(
        dbl, RNc, W_dt, Rc, dtb, DIc, M, DIc, Rc, dt_bias);

    // Selective scan -> y (bf16 hi/lo)
    scan_kernel<<<(Bc * DIc) / 16, 256>>>(dtb, dbl, xc, xz, A_log, D_param, yhi, ylo);

    // GEMM4 (tensor): out[M,1024] = y @ W_out^T
    gemm_mma<<<dim3(Dc / 128, M / 128), 256, TENSOR_SMEM>>>(
        yhi, ylo, wohi, wolo, out, DIc, Dc);
}

// round 7
// speedup vs baseline: 2.3180x; 1.1162x over previous
#include <cuda_runtime.h>
#include <cuda_bf16.h>
#include <math.h>
#include <stdint.h>

// Problem constants
#define Bc      4
#define Lc      2048
#define Dc      1024
#define DIc     2048
#define TWO_DIc 4096
#define Nc      16
#define Kc      4
#define Rc      64
#define RNc     96    // R + 2N

// fp32 scratch
__device__ float g_xz [(size_t)Bc * Lc * TWO_DIc];
__device__ float g_xc [(size_t)Bc * Lc * DIc];
__device__ float g_dbl[(size_t)Bc * Lc * RNc];
__device__ float g_dt [(size_t)Bc * Lc * DIc];

// bf16 split scratch (hi/lo)
__device__ __nv_bfloat16 g_xhi [(size_t)Bc * Lc * Dc];
__device__ __nv_bfloat16 g_xlo [(size_t)Bc * Lc * Dc];
__device__ __nv_bfloat16 g_wihi[(size_t)TWO_DIc * Dc];
__device__ __nv_bfloat16 g_wilo[(size_t)TWO_DIc * Dc];
__device__ __nv_bfloat16 g_yhi [(size_t)Bc * Lc * DIc];
__device__ __nv_bfloat16 g_ylo [(size_t)Bc * Lc * DIc];
__device__ __nv_bfloat16 g_wohi[(size_t)Dc * DIc];
__device__ __nv_bfloat16 g_wolo[(size_t)Dc * DIc];

// ---------------------------------------------------------------------------
// Helpers
// ---------------------------------------------------------------------------
__device__ __forceinline__ uint32_t smem_u32(const void* p) {
    uint32_t a;
    asm("{ .reg .u64 t; cvta.to.shared.u64 t, %1; cvt.u32.u64 %0, t; }"
        : "=r"(a) : "l"(p));
    return a;
}
__device__ __forceinline__ void cpa16(uint32_t dst, const void* src) {
    asm volatile("cp.async.cg.shared.global [%0], [%1], 16;"
                 :: "r"(dst), "l"(src) : "memory");
}
__device__ __forceinline__ void mma_bf16(float* c, const uint32_t* a, const uint32_t* b) {
    asm volatile(
        "mma.sync.aligned.m16n8k16.row.col.f32.bf16.bf16.f32 "
        "{%0,%1,%2,%3}, {%4,%5,%6,%7}, {%8,%9}, {%0,%1,%2,%3};"
        : "+f"(c[0]), "+f"(c[1]), "+f"(c[2]), "+f"(c[3])
        : "r"(a[0]), "r"(a[1]), "r"(a[2]), "r"(a[3]), "r"(b[0]), "r"(b[1]));
}
__device__ __forceinline__ void ldm_x4(uint32_t* r, uint32_t addr) {
    asm volatile("ldmatrix.sync.aligned.m8n8.x4.shared.b16 {%0,%1,%2,%3}, [%4];"
                 : "=r"(r[0]), "=r"(r[1]), "=r"(r[2]), "=r"(r[3]) : "r"(addr));
}
__device__ __forceinline__ void ldm_x2(uint32_t* r, uint32_t addr) {
    asm volatile("ldmatrix.sync.aligned.m8n8.x2.shared.b16 {%0,%1}, [%2];"
                 : "=r"(r[0]), "=r"(r[1]) : "r"(addr));
}

// ---------------------------------------------------------------------------
// Split fp32 -> bf16 hi/lo   (n % 4 == 0)
// ---------------------------------------------------------------------------
__global__ void split_kernel(const float* __restrict__ src,
                             __nv_bfloat16* __restrict__ hi,
                             __nv_bfloat16* __restrict__ lo, int n)
{
    const int i = (blockIdx.x * blockDim.x + threadIdx.x) * 4;
    if (i >= n) return;
    const float4 v = *reinterpret_cast<const float4*>(src + i);
    __nv_bfloat16 h[4], l[4];
    const float f[4] = {v.x, v.y, v.z, v.w};
    #pragma unroll
    for (int j = 0; j < 4; ++j) {
        h[j] = __float2bfloat16(f[j]);
        l[j] = __float2bfloat16(f[j] - __bfloat162float(h[j]));
    }
    *reinterpret_cast<__nv_bfloat162*>(hi + i)     = __nv_bfloat162(h[0], h[1]);
    *reinterpret_cast<__nv_bfloat162*>(hi + i + 2) = __nv_bfloat162(h[2], h[3]);
    *reinterpret_cast<__nv_bfloat162*>(lo + i)     = __nv_bfloat162(l[0], l[1]);
    *reinterpret_cast<__nv_bfloat162*>(lo + i + 2) = __nv_bfloat162(l[2], l[3]);
}

// ---------------------------------------------------------------------------
// Split-bf16 tensor-core GEMM via mma.sync (HMMA path).
//   C[m,n] = A[m,:]·B[n,:]  (NT); 3 passes Ahi*Bhi + Ahi*Blo + Alo*Bhi (fp32 acc)
// CTA 128x128, BK=32; 8 warps (2x4), warp tile 64x32; cp.async double buffer.
// ldmatrix fragment loads; 2 CTAs/SM via launch bounds (regs <= 128).
// ---------------------------------------------------------------------------
#define TSTAGE 40960
#define TROW   80      // smem row stride bytes (40 bf16); 16B-aligned rows

__global__ __launch_bounds__(256, 2)
void gemm_mma(const __nv_bfloat16* __restrict__ Ahi,
              const __nv_bfloat16* __restrict__ Alo,
              const __nv_bfloat16* __restrict__ Bhi,
              const __nv_bfloat16* __restrict__ Blo,
              float* __restrict__ C, int K, int ldc)
{
    extern __shared__ char smem[];
    const uint32_t sm0 = smem_u32(smem);
    const int tid  = threadIdx.x;
    const int wid  = tid >> 5;
    const int lane = tid & 31;
    const int wm   = wid >> 2;          // m offset wm*64
    const int wn   = wid & 3;           // n offset wn*32
    const int bm   = blockIdx.y * 128;
    const int bn   = blockIdx.x * 128;
    const int g    = lane >> 2;
    const int q    = lane & 3;

    // ldmatrix per-lane address offsets
    const uint32_t aoffL = (uint32_t)(lane & 15) * TROW + (uint32_t)(lane >> 4) * 16;
    const uint32_t boffL = (uint32_t)(lane & 7) * TROW + (uint32_t)((lane >> 3) & 1) * 16;

    float acc[4][4][4] = {};

    auto stage_load = [&](int kt, int s) {
        const uint32_t sb = sm0 + s * TSTAGE;
        #pragma unroll
        for (int i = 0; i < 2; ++i) {
            const int idx = tid + 256 * i;
            const int row = idx >> 2;
            const int c4  = idx & 3;
            const uint32_t so = (uint32_t)row * TROW + c4 * 16;
            const size_t goA = (size_t)(bm + row) * K + kt + c4 * 8;
            const size_t goB = (size_t)(bn + row) * K + kt + c4 * 8;
            cpa16(sb + so,         Ahi + goA);
            cpa16(sb + 10240 + so, Alo + goA);
            cpa16(sb + 20480 + so, Bhi + goB);
            cpa16(sb + 30720 + so, Blo + goB);
        }
        asm volatile("cp.async.commit_group;" ::: "memory");
    };

    stage_load(0, 0);

    const int nt_iters = K / 32;
    for (int t = 0; t < nt_iters; ++t) {
        asm volatile("cp.async.wait_group 0;" ::: "memory");
        __syncthreads();
        if (t + 1 < nt_iters) stage_load((t + 1) * 32, (t + 1) & 1);

        const uint32_t stg = sm0 + (t & 1) * TSTAGE;
        #pragma unroll
        for (int ks = 0; ks < 2; ++ks) {
            uint32_t a_hi[4][4], a_lo[4][4];
            #pragma unroll
            for (int mt = 0; mt < 4; ++mt) {
                const uint32_t ab = stg + (uint32_t)(wm * 64 + mt * 16) * TROW
                                        + ks * 32 + aoffL;
                ldm_x4(a_hi[mt], ab);
                ldm_x4(a_lo[mt], ab + 10240);
            }
            #pragma unroll
            for (int nt = 0; nt < 4; ++nt) {
                const uint32_t bb = stg + 20480 + (uint32_t)(wn * 32 + nt * 8) * TROW
                                        + ks * 32 + boffL;
                uint32_t bh[2], bl2[2];
                ldm_x2(bh,  bb);
                ldm_x2(bl2, bb + 10240);
                #pragma unroll
                for (int mt = 0; mt < 4; ++mt) {
                    mma_bf16(acc[mt][nt], a_hi[mt], bh);
                    mma_bf16(acc[mt][nt], a_hi[mt], bl2);
                    mma_bf16(acc[mt][nt], a_lo[mt], bh);
                }
            }
        }
        __syncthreads();
    }

    #pragma unroll
    for (int mt = 0; mt < 4; ++mt) {
        const int r0 = bm + wm * 64 + mt * 16 + g;
        #pragma unroll
        for (int nt = 0; nt < 4; ++nt) {
            const int c0 = bn + wn * 32 + nt * 8 + q * 2;
            *reinterpret_cast<float2*>(&C[(size_t)r0 * ldc + c0]) =
                make_float2(acc[mt][nt][0], acc[mt][nt][1]);
            *reinterpret_cast<float2*>(&C[(size_t)(r0 + 8) * ldc + c0]) =
                make_float2(acc[mt][nt][2], acc[mt][nt][3]);
        }
    }
}

// ---------------------------------------------------------------------------
// Packed f32x2 helpers
// ---------------------------------------------------------------------------
__device__ __forceinline__ unsigned long long pk2(float lo, float hi) {
    unsigned long long r;
    asm("mov.b64 %0, {%1, %2};" : "=l"(r) : "f"(lo), "f"(hi));
    return r;
}
__device__ __forceinline__ void fma2(unsigned long long& d,
                                     unsigned long long a, unsigned long long b) {
    asm("fma.rn.f32x2 %0, %1, %2, %0;" : "+l"(d) : "l"(a), "l"(b));
}
__device__ __forceinline__ float2 upk2(unsigned long long v) {
    float2 f;
    asm("mov.b64 {%0, %1}, %2;" : "=f"(f.x), "=f"(f.y) : "l"(v));
    return f;
}

// ---------------------------------------------------------------------------
// Scalar NT SGEMM (f32x2, double-buffered) — GEMM2/GEMM3
// ---------------------------------------------------------------------------
template<int BM, int BN, int BK, int TM, int TN, int EPI>
__global__ __launch_bounds__((BM / TM) * (BN / TN), 2)
void gemm_nt(const float* __restrict__ A, int lda,
             const float* __restrict__ Bw, int ldb,
             float* __restrict__ C, int ldc,
             int M, int Nn, int K,
             const float* __restrict__ bias)
{
    constexpr int THREADS = (BM / TM) * (BN / TN);
    constexpr int VPR     = BK / 4;
    constexpr int RS      = THREADS / VPR;
    constexpr int AR      = BM / RS;
    constexpr int BR      = BN / RS;
    constexpr int LDA_S   = BM + 4;
    constexpr int LDB_S   = BN + 4;

    __shared__ float As[2][BK][LDA_S];
    __shared__ float Bs[2][BK][LDB_S];

    const int tid = threadIdx.x;
    const int tx  = tid % (BN / TN);
    const int ty  = tid / (BN / TN);
    const int bm  = blockIdx.y * BM;
    const int bn  = blockIdx.x * BN;
    const int lr  = tid / VPR;
    const int lc  = (tid % VPR) * 4;

    unsigned long long acc[TM][TN / 2] = {};
    float4 ar[AR], br[BR];

    auto ldg = [&](int kt) {
        #pragma unroll
        for (int i = 0; i < AR; ++i)
            ar[i] = *reinterpret_cast<const float4*>(
                &A[(size_t)(bm + i * RS + lr) * lda + kt + lc]);
        #pragma unroll
        for (int i = 0; i < BR; ++i) {
            const int n = bn + i * RS + lr;
            br[i] = (n < Nn)
                  ? *reinterpret_cast<const float4*>(&Bw[(size_t)n * ldb + kt + lc])
                  : make_float4(0.f, 0.f, 0.f, 0.f);
        }
    };
    auto sts = [&](int s) {
        #pragma unroll
        for (int i = 0; i < AR; ++i) {
            As[s][lc + 0][i * RS + lr] = ar[i].x;
            As[s][lc + 1][i * RS + lr] = ar[i].y;
            As[s][lc + 2][i * RS + lr] = ar[i].z;
            As[s][lc + 3][i * RS + lr] = ar[i].w;
        }
        #pragma unroll
        for (int i = 0; i < BR; ++i) {
            Bs[s][lc + 0][i * RS + lr] = br[i].x;
            Bs[s][lc + 1][i * RS + lr] = br[i].y;
            Bs[s][lc + 2][i * RS + lr] = br[i].z;
            Bs[s][lc + 3][i * RS + lr] = br[i].w;
        }
    };

    ldg(0);
    sts(0);
    __syncthreads();

    const int nt = K / BK;
    for (int t = 0; t < nt; ++t) {
        const int cur = t & 1;
        if (t + 1 < nt) ldg((t + 1) * BK);

        #pragma unroll
        for (int k = 0; k < BK; ++k) {
            float4 af[TM / 4], bf[TN / 4];
            #pragma unroll
            for (int i = 0; i < TM / 4; ++i)
                af[i] = *reinterpret_cast<const float4*>(&As[cur][k][ty * TM + 4 * i]);
            #pragma unroll
            for (int j = 0; j < TN / 4; ++j)
                bf[j] = *reinterpret_cast<const float4*>(&Bs[cur][k][tx * TN + 4 * j]);

            unsigned long long bp[TN / 2];
            #pragma unroll
            for (int j = 0; j < TN / 4; ++j) {
                bp[2 * j]     = pk2(bf[j].x, bf[j].y);
                bp[2 * j + 1] = pk2(bf[j].z, bf[j].w);
            }
            const float* afs = reinterpret_cast<const float*>(af);
            #pragma unroll
            for (int i = 0; i < TM; ++i) {
                const unsigned long long a2 = pk2(afs[i], afs[i]);
                #pragma unroll
                for (int j = 0; j < TN / 2; ++j)
                    fma2(acc[i][j], a2, bp[j]);
            }
        }

        if (t + 1 < nt) sts((t + 1) & 1);
        __syncthreads();
    }

    #pragma unroll
    for (int i = 0; i < TM; ++i) {
        const int row = bm + ty * TM + i;
        #pragma unroll
        for (int j = 0; j < TN / 2; ++j) {
            const int col = bn + tx * TN + 2 * j;
            if (col < Nn) {
                float2 p = upk2(acc[i][j]);
                if (EPI == 1) {
                    p.x += bias[col];
                    p.x = (p.x > 20.f) ? p.x : log1pf(__expf(p.x));
                    p.y += bias[col + 1];
                    p.y = (p.y > 20.f) ? p.y : log1pf(__expf(p.y));
                }
                *reinterpret_cast<float2*>(&C[(size_t)row * ldc + col]) = p;
            }
        }
    }
}

// ---------------------------------------------------------------------------
// Depthwise causal conv (K=4) + bias + silu
// ---------------------------------------------------------------------------
__global__ void conv_silu_kernel(const float* __restrict__ xz,
                                 const float* __restrict__ conv_w,
                                 const float* __restrict__ conv_b,
                                 float* __restrict__ xc)
{
    const int d = blockIdx.x * blockDim.x + threadIdx.x;
    const int l = blockIdx.y;
    const int b = blockIdx.z;

    float accv = conv_b[d];
    #pragma unroll
    for (int k = 0; k < Kc; ++k) {
        const int ls = l - (Kc - 1) + k;
        if (ls >= 0)
            accv = fmaf(xz[((size_t)b * Lc + ls) * TWO_DIc + d],
                        conv_w[d * Kc + k], accv);
    }
    const float s = accv / (1.f + __expf(-accv));
    xc[((size_t)b * Lc + l) * DIc + d] = s;
}

// ---------------------------------------------------------------------------
// Selective scan, 2-deep software pipeline; emits y as bf16 hi/lo
// ---------------------------------------------------------------------------
__global__ void scan_kernel(const float* __restrict__ dt,
                            const float* __restrict__ dbl,
                            const float* __restrict__ xc,
                            const float* __restrict__ xz,
                            const float* __restrict__ A_log,
                            const float* __restrict__ D_param,
                            __nv_bfloat16* __restrict__ yhi,
                            __nv_bfloat16* __restrict__ ylo)
{
    const int gid  = blockIdx.x * (blockDim.x >> 4) + (threadIdx.x >> 4);
    const int lane = threadIdx.x & 15;
    const int b = gid / DIc;
    const int d = gid % DIc;

    const float An = -__expf(A_log[d * Nc + lane]);
    const float Dd = D_param[d];
    float h = 0.f;

    const float* dt_p = dt  + (size_t)b * Lc * DIc + d;
    const float* xc_p = xc  + (size_t)b * Lc * DIc + d;
    const float* z_p  = xz  + (size_t)b * Lc * TWO_DIc + DIc + d;
    const float* bc_p = dbl + (size_t)b * Lc * RNc + Rc;
    __nv_bfloat16* yh_p = yhi + (size_t)b * Lc * DIc + d;
    __nv_bfloat16* yl_p = ylo + (size_t)b * Lc * DIc + d;

    float dt0 = dt_p[0],       dt1 = dt_p[DIc];
    float xc0 = xc_p[0],       xc1 = xc_p[DIc];
    float B0  = bc_p[lane],    B1  = bc_p[RNc + lane];
    float C0  = bc_p[Nc+lane], C1  = bc_p[RNc + Nc + lane];
    float z0  = z_p[0],        z1  = z_p[TWO_DIc];

    for (int l = 0; l < Lc; l += 2) {
        float dt2 = 0.f, xc2 = 0.f, B2 = 0.f, C2 = 0.f, z2 = 0.f;
        float dt3 = 0.f, xc3 = 0.f, B3 = 0.f, C3 = 0.f, z3 = 0.f;
        if (l + 2 < Lc) {
            dt2 = dt_p[(size_t)(l + 2) * DIc];
            xc2 = xc_p[(size_t)(l + 2) * DIc];
            B2  = bc_p[(size_t)(l + 2) * RNc + lane];
            C2  = bc_p[(size_t)(l + 2) * RNc + Nc + lane];
            z2  = z_p[(size_t)(l + 2) * TWO_DIc];
            dt3 = dt_p[(size_t)(l + 3) * DIc];
            xc3 = xc_p[(size_t)(l + 3) * DIc];
            B3  = bc_p[(size_t)(l + 3) * RNc + lane];
            C3  = bc_p[(size_t)(l + 3) * RNc + Nc + lane];
            z3  = z_p[(size_t)(l + 3) * TWO_DIc];
        }

        // timestep l
        {
            const float dA = __expf(dt0 * An);
            h = fmaf(dA, h, dt0 * B0 * xc0);
            float v = h * C0;
            v += __shfl_xor_sync(0xffffffffu, v, 8);
            v += __shfl_xor_sync(0xffffffffu, v, 4);
            v += __shfl_xor_sync(0xffffffffu, v, 2);
            v += __shfl_xor_sync(0xffffffffu, v, 1);
            if (lane == 0) {
                float yv = (v + xc0 * Dd) * (z0 / (1.f + __expf(-z0)));
                const __nv_bfloat16 hh = __float2bfloat16(yv);
                yh_p[(size_t)l * DIc] = hh;
                yl_p[(size_t)l * DIc] = __float2bfloat16(yv - __bfloat162float(hh));
            }
        }
        // timestep l+1
        {
            const float dA = __expf(dt1 * An);
            h = fmaf(dA, h, dt1 * B1 * xc1);
            float v = h * C1;
            v += __shfl_xor_sync(0xffffffffu, v, 8);
            v += __shfl_xor_sync(0xffffffffu, v, 4);
            v += __shfl_xor_sync(0xffffffffu, v, 2);
            v += __shfl_xor_sync(0xffffffffu, v, 1);
            if (lane == 0) {
                float yv = (v + xc1 * Dd) * (z1 / (1.f + __expf(-z1)));
                const __nv_bfloat16 hh = __float2bfloat16(yv);
                yh_p[(size_t)(l + 1) * DIc] = hh;
                yl_p[(size_t)(l + 1) * DIc] = __float2bfloat16(yv - __bfloat162float(hh));
            }
        }

        dt0 = dt2; xc0 = xc2; B0 = B2; C0 = C2; z0 = z2;
        dt1 = dt3; xc1 = xc3; B1 = B3; C1 = C3; z1 = z3;
    }
}

// ---------------------------------------------------------------------------
extern "C" void kernel_launch(void* const* d_in, const int* in_sizes, int n_in,
                              void* d_out, int out_size)
{
    const float* x       = (const float*)d_in[0];
    const float* W_in    = (const float*)d_in[1];
    const float* conv_w  = (const float*)d_in[2];
    const float* conv_b  = (const float*)d_in[3];
    const float* W_xproj = (const float*)d_in[4];
    const float* W_dt    = (const float*)d_in[5];
    const float* dt_bias = (const float*)d_in[6];
    const float* A_log   = (const float*)d_in[7];
    const float* D_param = (const float*)d_in[8];
    const float* W_out   = (const float*)d_in[9];
    float* out = (float*)d_out;

    float *xz, *xc, *dbl, *dtb;
    __nv_bfloat16 *xhi, *xlo, *wihi, *wilo, *yhi, *ylo, *wohi, *wolo;
    cudaGetSymbolAddress((void**)&xz,   g_xz);
    cudaGetSymbolAddress((void**)&xc,   g_xc);
    cudaGetSymbolAddress((void**)&dbl,  g_dbl);
    cudaGetSymbolAddress((void**)&dtb,  g_dt);
    cudaGetSymbolAddress((void**)&xhi,  g_xhi);
    cudaGetSymbolAddress((void**)&xlo,  g_xlo);
    cudaGetSymbolAddress((void**)&wihi, g_wihi);
    cudaGetSymbolAddress((void**)&wilo, g_wilo);
    cudaGetSymbolAddress((void**)&yhi,  g_yhi);
    cudaGetSymbolAddress((void**)&ylo,  g_ylo);
    cudaGetSymbolAddress((void**)&wohi, g_wohi);
    cudaGetSymbolAddress((void**)&wolo, g_wolo);

    const int M = Bc * Lc;  // 8192
    const int TENSOR_SMEM = 2 * TSTAGE;  // 81920 B

    cudaFuncSetAttribute(gemm_mma,
                         cudaFuncAttributeMaxDynamicSharedMemorySize, TENSOR_SMEM);

    // Split inputs to bf16 hi/lo
    split_kernel<<<(M * Dc / 4 + 255) / 256, 256>>>(x, xhi, xlo, M * Dc);
    split_kernel<<<(TWO_DIc * Dc / 4 + 255) / 256, 256>>>(W_in, wihi, wilo, TWO_DIc * Dc);
    split_kernel<<<(Dc * DIc / 4 + 255) / 256, 256>>>(W_out, wohi, wolo, Dc * DIc);

    // GEMM1 (tensor): xz[M,4096] = x @ W_in^T
    gemm_mma<<<dim3(TWO_DIc / 128, M / 128), 256, TENSOR_SMEM>>>(
        xhi, xlo, wihi, wilo, xz, Dc, TWO_DIc);

    // Depthwise causal conv + silu -> xc
    conv_silu_kernel<<<dim3(DIc / 256, Lc, Bc), 256>>>(xz, conv_w, conv_b, xc);

    // GEMM2 (scalar): dbl[M,96] = xc @ W_xproj^T  (BM=32 -> 256 CTAs)
    gemm_nt<32, 128, 16, 4, 8, 0><<<dim3(1, M / 32), 128>>>(
        xc, DIc, W_xproj, DIc, dbl, RNc, M, RNc, DIc, nullptr);

    // GEMM3 (scalar): dt[M,2048] = softplus(dbl[:, :64] @ W_dt^T + dt_bias)
    gemm_nt<128, 128, 16, 8, 8, 1><<<dim3(DIc / 128, M / 128), 256>>>(
        dbl, RNc, W_dt, Rc, dtb, DIc, M, DIc, Rc, dt_bias);

    // Selective scan -> y (bf16 hi/lo)
    scan_kernel<<<(Bc * DIc) / 16, 256>>>(dtb, dbl, xc, xz, A_log, D_param, yhi, ylo);

    // GEMM4 (tensor): out[M,1024] = y @ W_out^T
    gemm_mma<<<dim3(Dc / 128, M / 128), 256, TENSOR_SMEM>>>(
        yhi, ylo, wohi, wolo, out, DIc, Dc);
}